// round 3
// baseline (speedup 1.0000x reference)
#include <cuda_runtime.h>
#include <cuda_bf16.h>
#include <math.h>

#define RAYS    8192
#define SAMPLES 256
#define GRIDN   160
#define HID     128
#define KPAIRS  20          // (39 inputs padded to 40) / 2
#define ACT_SHIFT (-13.815509557964274f)

// ---------------- shared memory layout (bytes) ----------------
#define SZ_W1   (HID*64*4)       // bf16x2[128*64]  = 32768
#define SZ_W0T  (HID*KPAIRS*4)   // bf16x2[128*20]  = 10240
#define SZ_H    (HID*SAMPLES*2)  // bf16 [128][256] = 65536
#define SZ_W2   (HID*3*4)        // 1536
#define SZ_B0   (HID*4)          // 512
#define SZ_B1P  (64*4)           // 256
#define SZ_SCAN (SAMPLES*4)      // 1024 (x2)
#define SZ_VEMF (32*4)           // 128
#define SZ_VEM2 (16*4)           // 64

#define OFF_W1   0
#define OFF_W0T  (OFF_W1   + SZ_W1)
#define OFF_H    (OFF_W0T  + SZ_W0T)
#define OFF_W2   (OFF_H    + SZ_H)
#define OFF_B0   (OFF_W2   + SZ_W2)
#define OFF_B1P  (OFF_B0   + SZ_B0)
#define OFF_SCA  (OFF_B1P  + SZ_B1P)
#define OFF_SCB  (OFF_SCA  + SZ_SCAN)
#define OFF_VEMF (OFF_SCB  + SZ_SCAN)
#define OFF_VEM2 (OFF_VEMF + SZ_VEMF)
#define SMEM_TOTAL (OFF_VEM2 + SZ_VEM2)   // 113088 bytes

extern "C" __global__ void __launch_bounds__(256)
dvgo_fused_kernel(const float* __restrict__ ray_pts,
                  const float* __restrict__ viewdirs,
                  const float* __restrict__ dgrid,
                  const float* __restrict__ k0,
                  const float* __restrict__ w0,
                  const float* __restrict__ b0,
                  const float* __restrict__ w1,
                  const float* __restrict__ b1,
                  const float* __restrict__ w2,
                  const float* __restrict__ b2,
                  float* __restrict__ out)
{
    extern __shared__ char smem[];
    __nv_bfloat162* s_w1  = (__nv_bfloat162*)(smem + OFF_W1);
    __nv_bfloat162* s_w0t = (__nv_bfloat162*)(smem + OFF_W0T);
    __nv_bfloat16*  s_h   = (__nv_bfloat16*) (smem + OFF_H);
    float*          s_w2  = (float*)         (smem + OFF_W2);
    float*          s_b0  = (float*)         (smem + OFF_B0);
    __nv_bfloat162* s_b1p = (__nv_bfloat162*)(smem + OFF_B1P);
    float*          sA    = (float*)         (smem + OFF_SCA);
    float*          sB    = (float*)         (smem + OFF_SCB);
    float*          s_vf  = (float*)         (smem + OFF_VEMF);
    __nv_bfloat162* s_v2  = (__nv_bfloat162*)(smem + OFF_VEM2);

    const int tid = threadIdx.x;
    const int ray = blockIdx.x;

    // ---------------- cooperative weight staging ----------------
    // w1: pairs along output dim j -> s_w1[k*64 + jp] = (w1[k][2jp], w1[k][2jp+1])
    const float2* w1v = (const float2*)w1;
    for (int i = tid; i < HID * 64; i += 256) {
        float2 v = w1v[i];
        s_w1[i] = __floats2bfloat162_rn(v.x, v.y);
    }
    // w0 transposed + paired along input dim k: s_w0t[j*20+p] = (w0[2p][j], w0[2p+1][j])
    for (int i = tid; i < HID * KPAIRS; i += 256) {
        int j = i / KPAIRS, p = i % KPAIRS;
        int ka = 2 * p, kb = 2 * p + 1;
        float lo = (ka < 39) ? w0[ka * HID + j] : 0.0f;
        float hi = (kb < 39) ? w0[kb * HID + j] : 0.0f;
        s_w0t[i] = __floats2bfloat162_rn(lo, hi);
    }
    for (int i = tid; i < HID * 3; i += 256) s_w2[i] = w2[i];
    if (tid < HID) s_b0[tid] = b0[tid];
    if (tid < 64)  s_b1p[tid] = __floats2bfloat162_rn(b1[2 * tid], b1[2 * tid + 1]);

    // ---------------- view embedding (per ray, 27 values) ----------------
    if (tid < 28) {
        float vx = viewdirs[ray * 3 + 0];
        float vy = viewdirs[ray * 3 + 1];
        float vz = viewdirs[ray * 3 + 2];
        float inv = 1.0f / (sqrtf(vx * vx + vy * vy + vz * vz) + 1e-10f);
        float d0 = vx * inv, d1 = vy * inv, d2 = vz * inv;
        float dd[3] = {d0, d1, d2};
        float val;
        if (tid < 3) {
            val = dd[tid];
        } else if (tid < 15) {
            int m = tid - 3;
            val = sinf(dd[m >> 2] * (float)(1 << (m & 3)));
        } else if (tid < 27) {
            int m = tid - 15;
            val = cosf(dd[m >> 2] * (float)(1 << (m & 3)));
        } else {
            val = 0.0f;
        }
        s_vf[tid] = val;
    }
    __syncthreads();
    if (tid < 14) s_v2[tid] = __floats2bfloat162_rn(s_vf[2 * tid], s_vf[2 * tid + 1]);
    // (next __syncthreads below covers s_v2 visibility)

    // ---------------- per-sample point + density trilinear ----------------
    const int pidx = (ray * SAMPLES + tid) * 3;
    float px = ray_pts[pidx + 0];
    float py = ray_pts[pidx + 1];
    float pz = ray_pts[pidx + 2];

    float gx = fminf(fmaxf(px, 0.0f), 1.0f) * 159.0f;
    float gy = fminf(fmaxf(py, 0.0f), 1.0f) * 159.0f;
    float gz = fminf(fmaxf(pz, 0.0f), 1.0f) * 159.0f;
    int ix = (int)floorf(gx); ix = max(0, min(ix, 158));
    int iy = (int)floorf(gy); iy = max(0, min(iy, 158));
    int iz = (int)floorf(gz); iz = max(0, min(iz, 158));
    float fx = gx - (float)ix, fy = gy - (float)iy, fz = gz - (float)iz;

    const int base = (ix * GRIDN + iy) * GRIDN + iz;
    const float wx0 = 1.0f - fx, wx1 = fx;
    const float wy0 = 1.0f - fy, wy1 = fy;
    const float wz0 = 1.0f - fz, wz1 = fz;

    const int XS = GRIDN * GRIDN;  // x stride
    float d000 = __ldg(dgrid + base);
    float d001 = __ldg(dgrid + base + 1);
    float d010 = __ldg(dgrid + base + GRIDN);
    float d011 = __ldg(dgrid + base + GRIDN + 1);
    float d100 = __ldg(dgrid + base + XS);
    float d101 = __ldg(dgrid + base + XS + 1);
    float d110 = __ldg(dgrid + base + XS + GRIDN);
    float d111 = __ldg(dgrid + base + XS + GRIDN + 1);

    float den = wx0 * (wy0 * (wz0 * d000 + wz1 * d001) +
                       wy1 * (wz0 * d010 + wz1 * d011)) +
                wx1 * (wy0 * (wz0 * d100 + wz1 * d101) +
                       wy1 * (wz0 * d110 + wz1 * d111));

    float e = expf(den + ACT_SHIFT);
    float alpha = 1.0f - 1.0f / sqrtf(1.0f + e);   // (1+e)^(-0.5), matches reference fp32 path
    float t = 1.0f - alpha + 1e-10f;
    sA[tid] = t;
    __syncthreads();

    // ---------------- block-wide inclusive product scan (cumprod) ----------------
    float v = t;
    float* cur = sA;
    float* nxt = sB;
    #pragma unroll
    for (int off = 1; off < SAMPLES; off <<= 1) {
        if (tid >= off) v *= cur[tid - off];
        nxt[tid] = v;
        __syncthreads();
        float* tmp = cur; cur = nxt; nxt = tmp;
    }
    float T_excl    = (tid == 0) ? 1.0f : cur[tid - 1];
    float ainv_last = cur[SAMPLES - 1];
    float wgt       = alpha * T_excl;

    // ---------------- feature trilinear (12 channels, float4 gathers) ----------------
    const float4* k0v = (const float4*)k0;
    float ft[12];
    #pragma unroll
    for (int c = 0; c < 12; c++) ft[c] = 0.0f;

    #pragma unroll
    for (int cx = 0; cx < 2; cx++) {
        float wxa = cx ? wx1 : wx0;
        #pragma unroll
        for (int cy = 0; cy < 2; cy++) {
            float wxy = wxa * (cy ? wy1 : wy0);
            #pragma unroll
            for (int cz = 0; cz < 2; cz++) {
                float wc = wxy * (cz ? wz1 : wz0);
                int idx = base + cx * XS + cy * GRIDN + cz;
                int b3 = idx * 3;  // float4 units (12 floats = 3 x float4, 48B aligned)
                float4 qa = __ldg(k0v + b3);
                float4 qb = __ldg(k0v + b3 + 1);
                float4 qc = __ldg(k0v + b3 + 2);
                ft[0]  += wc * qa.x;  ft[1]  += wc * qa.y;
                ft[2]  += wc * qa.z;  ft[3]  += wc * qa.w;
                ft[4]  += wc * qb.x;  ft[5]  += wc * qb.y;
                ft[6]  += wc * qb.z;  ft[7]  += wc * qb.w;
                ft[8]  += wc * qc.x;  ft[9]  += wc * qc.y;
                ft[10] += wc * qc.z;  ft[11] += wc * qc.w;
            }
        }
    }

    // ---------------- build bf16 input pairs: x = [feat(12), vemb(27), pad] ----------------
    __nv_bfloat162 x2[KPAIRS];
    #pragma unroll
    for (int p = 0; p < 6; p++)
        x2[p] = __floats2bfloat162_rn(ft[2 * p], ft[2 * p + 1]);
    #pragma unroll
    for (int p = 0; p < 14; p++)
        x2[6 + p] = s_v2[p];

    // ---------------- layer 0: h[j] = relu(x . w0[:,j] + b0[j]) -> shared bf16 ----------------
    // Weight row = 20 bf16x2 = 80B, 16B-aligned -> 5 LDS.128 (broadcast) per j.
    for (int j = 0; j < HID; j++) {
        const float4* wr4 = (const float4*)(s_w0t + j * KPAIRS);
        __nv_bfloat162 a = __floats2bfloat162_rn(s_b0[j], 0.0f);
        #pragma unroll
        for (int q = 0; q < 5; q++) {
            float4 w4 = wr4[q];
            a = __hfma2(x2[4 * q + 0], *(const __nv_bfloat162*)&w4.x, a);
            a = __hfma2(x2[4 * q + 1], *(const __nv_bfloat162*)&w4.y, a);
            a = __hfma2(x2[4 * q + 2], *(const __nv_bfloat162*)&w4.z, a);
            a = __hfma2(x2[4 * q + 3], *(const __nv_bfloat162*)&w4.w, a);
        }
        float hj = __low2float(a) + __high2float(a);
        s_h[j * SAMPLES + tid] = __float2bfloat16(fmaxf(hj, 0.0f));
    }

    // ---------------- layer 1: 128x128 GEMV per thread, 64 bf16x2 accumulators ----------------
    // Weight row = 64 bf16x2 = 256B -> 16 LDS.128 (broadcast) per k.
    __nv_bfloat162 acc[64];
    #pragma unroll
    for (int jp = 0; jp < 64; jp++) acc[jp] = s_b1p[jp];

    for (int k = 0; k < HID; k++) {
        __nv_bfloat162 h2 = __bfloat162bfloat162(s_h[k * SAMPLES + tid]);
        const float4* wr4 = (const float4*)(s_w1 + k * 64);
        #pragma unroll
        for (int q = 0; q < 16; q++) {
            float4 w4 = wr4[q];
            acc[4 * q + 0] = __hfma2(h2, *(const __nv_bfloat162*)&w4.x, acc[4 * q + 0]);
            acc[4 * q + 1] = __hfma2(h2, *(const __nv_bfloat162*)&w4.y, acc[4 * q + 1]);
            acc[4 * q + 2] = __hfma2(h2, *(const __nv_bfloat162*)&w4.z, acc[4 * q + 2]);
            acc[4 * q + 3] = __hfma2(h2, *(const __nv_bfloat162*)&w4.w, acc[4 * q + 3]);
        }
    }

    // ---------------- layer 2 (fused): rgb = sigmoid(relu(h1) @ w2 + b2) ----------------
    float r0 = __ldg(b2 + 0), r1 = __ldg(b2 + 1), r2 = __ldg(b2 + 2);
    #pragma unroll
    for (int jp = 0; jp < 64; jp++) {
        float a0 = fmaxf(__low2float(acc[jp]),  0.0f);
        float a1 = fmaxf(__high2float(acc[jp]), 0.0f);
        const float* wj = s_w2 + 6 * jp;
        r0 += a0 * wj[0] + a1 * wj[3];
        r1 += a0 * wj[1] + a1 * wj[4];
        r2 += a0 * wj[2] + a1 * wj[5];
    }
    float o0 = wgt * (1.0f / (1.0f + expf(-r0)));
    float o1 = wgt * (1.0f / (1.0f + expf(-r1)));
    float o2 = wgt * (1.0f / (1.0f + expf(-r2)));

    // ---------------- block reduction over samples ----------------
    #pragma unroll
    for (int s = 16; s > 0; s >>= 1) {
        o0 += __shfl_down_sync(0xffffffffu, o0, s);
        o1 += __shfl_down_sync(0xffffffffu, o1, s);
        o2 += __shfl_down_sync(0xffffffffu, o2, s);
    }
    __syncthreads();  // scan buffers no longer needed; reuse sA
    if ((tid & 31) == 0) {
        int w = tid >> 5;
        sA[w * 3 + 0] = o0;
        sA[w * 3 + 1] = o1;
        sA[w * 3 + 2] = o2;
    }
    __syncthreads();
    if (tid == 0) {
        float a0 = 0.0f, a1 = 0.0f, a2 = 0.0f;
        #pragma unroll
        for (int w = 0; w < 8; w++) {
            a0 += sA[w * 3 + 0];
            a1 += sA[w * 3 + 1];
            a2 += sA[w * 3 + 2];
        }
        out[ray * 3 + 0] = a0 + ainv_last;
        out[ray * 3 + 1] = a1 + ainv_last;
        out[ray * 3 + 2] = a2 + ainv_last;
    }
}

extern "C" void kernel_launch(void* const* d_in, const int* in_sizes, int n_in,
                              void* d_out, int out_size)
{
    const float* ray_pts  = (const float*)d_in[0];
    const float* viewdirs = (const float*)d_in[1];
    const float* dgrid    = (const float*)d_in[2];
    const float* k0       = (const float*)d_in[3];
    const float* w0       = (const float*)d_in[4];
    const float* b0       = (const float*)d_in[5];
    const float* w1       = (const float*)d_in[6];
    const float* b1       = (const float*)d_in[7];
    const float* w2       = (const float*)d_in[8];
    const float* b2       = (const float*)d_in[9];
    float* out = (float*)d_out;

    cudaFuncSetAttribute(dvgo_fused_kernel,
                         cudaFuncAttributeMaxDynamicSharedMemorySize, SMEM_TOTAL);
    dvgo_fused_kernel<<<RAYS, 256, SMEM_TOTAL>>>(
        ray_pts, viewdirs, dgrid, k0, w0, b0, w1, b1, w2, b2, out);
}

// round 9
// speedup vs baseline: 2.6614x; 2.6614x over previous
#include <cuda_runtime.h>
#include <cuda_bf16.h>
#include <cstdint>
#include <math.h>

#define RAYS    8192
#define SAMPLES 256
#define GRIDN   160
#define ACT_SHIFT (-13.815509557964274f)

// ---------------- SMEM layout (bytes) ----------------
// strides chosen so B-fragment LDS (n varies by lane>>2) hits distinct banks:
// word-stride % 32 == 4  ->  bank = 4*gid + q  (all 32 lanes distinct)
#define W1P_STRIDE 68    // words per n-row (64 data + pad)
#define W0P_STRIDE 28    // words per n-row (24 data + pad)
#define X_STRIDE   28    // words per sample row (20 data + pad)

#define OFF_W1P  0                        // 128*68*4 = 34816
#define OFF_W0P  34816                    // 128*28*4 = 14336
#define OFF_X    49152                    // 256*28*4 = 28672
#define OFF_B0   77824                    // 512
#define OFF_B1   78336                    // 512
#define OFF_W2P  78848                    // float4[128] = 2048
#define OFF_SCA  80896                    // 1024
#define OFF_SCB  81920                    // 1024
#define OFF_WGT  82944                    // 1024
#define OFF_VEMF 83968                    // 128
#define OFF_V2   84096                    // 64
#define OFF_RED  84160                    // 96
#define SMEM_DYN 84256

__device__ __forceinline__ void mma16816(float& c0, float& c1, float& c2, float& c3,
                                         uint32_t a0, uint32_t a1, uint32_t a2, uint32_t a3,
                                         uint32_t b0, uint32_t b1) {
    asm volatile("mma.sync.aligned.m16n8k16.row.col.f32.bf16.bf16.f32 "
                 "{%0,%1,%2,%3}, {%4,%5,%6,%7}, {%8,%9}, {%0,%1,%2,%3};"
                 : "+f"(c0), "+f"(c1), "+f"(c2), "+f"(c3)
                 : "r"(a0), "r"(a1), "r"(a2), "r"(a3), "r"(b0), "r"(b1));
}

__device__ __forceinline__ uint32_t packbf2(float lo, float hi) {
    __nv_bfloat162 b = __floats2bfloat162_rn(lo, hi);
    return *(uint32_t*)&b;
}

extern "C" __global__ void __launch_bounds__(256, 2)
dvgo_hmma_kernel(const float* __restrict__ ray_pts,
                 const float* __restrict__ viewdirs,
                 const float* __restrict__ dgrid,
                 const float* __restrict__ k0,
                 const float* __restrict__ w0,
                 const float* __restrict__ b0,
                 const float* __restrict__ w1,
                 const float* __restrict__ b1,
                 const float* __restrict__ w2,
                 const float* __restrict__ b2,
                 float* __restrict__ out)
{
    extern __shared__ char smem[];
    uint32_t* s_w1p = (uint32_t*)(smem + OFF_W1P);
    uint32_t* s_w0p = (uint32_t*)(smem + OFF_W0P);
    uint32_t* s_x   = (uint32_t*)(smem + OFF_X);
    float*    s_b0  = (float*)(smem + OFF_B0);
    float*    s_b1  = (float*)(smem + OFF_B1);
    float4*   s_w2p = (float4*)(smem + OFF_W2P);
    float*    sA    = (float*)(smem + OFF_SCA);
    float*    sB    = (float*)(smem + OFF_SCB);
    float*    s_wgt = (float*)(smem + OFF_WGT);
    float*    s_vf  = (float*)(smem + OFF_VEMF);
    __nv_bfloat162* s_v2 = (__nv_bfloat162*)(smem + OFF_V2);
    float*    s_red = (float*)(smem + OFF_RED);

    const int tid = threadIdx.x;
    const int ray = blockIdx.x;
    const int lane = tid & 31;
    const int warp = tid >> 5;
    const int gid = lane >> 2;     // group id (row within 8)
    const int q   = lane & 3;      // quad lane

    // ---------------- stage weights (k-paired bf16x2, transposed to n-major) ----------------
    // s_w1p[n*68 + kp] = (w1[2kp][n], w1[2kp+1][n])
    for (int i = tid; i < 128 * 64; i += 256) {
        int n = i & 127, kp = i >> 7;
        s_w1p[n * W1P_STRIDE + kp] = packbf2(w1[(2 * kp) * 128 + n],
                                             (w1[(2 * kp + 1) * 128 + n]));
    }
    // s_w0p[n*28 + kp] = (w0[2kp][n], w0[2kp+1][n]); k>=39 zero (in_dim=39, K padded to 48)
    for (int i = tid; i < 128 * 24; i += 256) {
        int n = i & 127, kp = i >> 7;
        int ka = 2 * kp, kb = 2 * kp + 1;
        float lo = (ka < 39) ? w0[ka * 128 + n] : 0.0f;
        float hi = (kb < 39) ? w0[kb * 128 + n] : 0.0f;
        s_w0p[n * W0P_STRIDE + kp] = packbf2(lo, hi);
    }
    if (tid < 128) {
        s_b0[tid] = b0[tid];
        s_b1[tid] = b1[tid];
        float4 w; w.x = w2[tid * 3]; w.y = w2[tid * 3 + 1]; w.z = w2[tid * 3 + 2]; w.w = 0.0f;
        s_w2p[tid] = w;
    }

    // ---------------- view embedding (per ray) ----------------
    if (tid < 28) {
        float vx = viewdirs[ray * 3 + 0];
        float vy = viewdirs[ray * 3 + 1];
        float vz = viewdirs[ray * 3 + 2];
        float inv = 1.0f / (sqrtf(vx * vx + vy * vy + vz * vz) + 1e-10f);
        float dd[3] = {vx * inv, vy * inv, vz * inv};
        float val;
        if (tid < 3)       val = dd[tid];
        else if (tid < 15) { int m = tid - 3;  val = sinf(dd[m >> 2] * (float)(1 << (m & 3))); }
        else if (tid < 27) { int m = tid - 15; val = cosf(dd[m >> 2] * (float)(1 << (m & 3))); }
        else               val = 0.0f;
        s_vf[tid] = val;
    }

    // ---------------- density trilinear + alpha (fp32, accuracy-critical) ----------------
    const int pidx = (ray * SAMPLES + tid) * 3;
    float px = ray_pts[pidx + 0];
    float py = ray_pts[pidx + 1];
    float pz = ray_pts[pidx + 2];

    float gx = fminf(fmaxf(px, 0.0f), 1.0f) * 159.0f;
    float gy = fminf(fmaxf(py, 0.0f), 1.0f) * 159.0f;
    float gz = fminf(fmaxf(pz, 0.0f), 1.0f) * 159.0f;
    int ix = (int)floorf(gx); ix = max(0, min(ix, 158));
    int iy = (int)floorf(gy); iy = max(0, min(iy, 158));
    int iz = (int)floorf(gz); iz = max(0, min(iz, 158));
    float fx = gx - (float)ix, fy = gy - (float)iy, fz = gz - (float)iz;

    const int base = (ix * GRIDN + iy) * GRIDN + iz;
    const float wx0 = 1.0f - fx, wx1 = fx;
    const float wy0 = 1.0f - fy, wy1 = fy;
    const float wz0 = 1.0f - fz, wz1 = fz;
    const int XS = GRIDN * GRIDN;

    float d000 = __ldg(dgrid + base);
    float d001 = __ldg(dgrid + base + 1);
    float d010 = __ldg(dgrid + base + GRIDN);
    float d011 = __ldg(dgrid + base + GRIDN + 1);
    float d100 = __ldg(dgrid + base + XS);
    float d101 = __ldg(dgrid + base + XS + 1);
    float d110 = __ldg(dgrid + base + XS + GRIDN);
    float d111 = __ldg(dgrid + base + XS + GRIDN + 1);

    float den = wx0 * (wy0 * (wz0 * d000 + wz1 * d001) +
                       wy1 * (wz0 * d010 + wz1 * d011)) +
                wx1 * (wy0 * (wz0 * d100 + wz1 * d101) +
                       wy1 * (wz0 * d110 + wz1 * d111));

    float e = expf(den + ACT_SHIFT);
    float alpha = 1.0f - 1.0f / sqrtf(1.0f + e);
    float t = 1.0f - alpha + 1e-10f;
    sA[tid] = t;
    __syncthreads();
    if (tid < 14) s_v2[tid] = __floats2bfloat162_rn(s_vf[2 * tid], s_vf[2 * tid + 1]);

    // ---------------- cumprod scan ----------------
    float v = t;
    float* cur = sA;
    float* nxt = sB;
    #pragma unroll
    for (int off = 1; off < SAMPLES; off <<= 1) {
        if (tid >= off) v *= cur[tid - off];
        nxt[tid] = v;
        __syncthreads();
        float* tmp = cur; cur = nxt; nxt = tmp;
    }
    float T_excl    = (tid == 0) ? 1.0f : cur[tid - 1];
    float ainv_last = cur[SAMPLES - 1];
    s_wgt[tid] = alpha * T_excl;

    // ---------------- feature trilinear (12 ch) ----------------
    const float4* k0v = (const float4*)k0;
    float ft[12];
    #pragma unroll
    for (int c = 0; c < 12; c++) ft[c] = 0.0f;
    #pragma unroll
    for (int cx = 0; cx < 2; cx++) {
        float wxa = cx ? wx1 : wx0;
        #pragma unroll
        for (int cy = 0; cy < 2; cy++) {
            float wxy = wxa * (cy ? wy1 : wy0);
            #pragma unroll
            for (int cz = 0; cz < 2; cz++) {
                float wc = wxy * (cz ? wz1 : wz0);
                int idx = base + cx * XS + cy * GRIDN + cz;
                int b3 = idx * 3;
                float4 qa = __ldg(k0v + b3);
                float4 qb = __ldg(k0v + b3 + 1);
                float4 qc = __ldg(k0v + b3 + 2);
                ft[0]  += wc * qa.x;  ft[1]  += wc * qa.y;
                ft[2]  += wc * qa.z;  ft[3]  += wc * qa.w;
                ft[4]  += wc * qb.x;  ft[5]  += wc * qb.y;
                ft[6]  += wc * qb.z;  ft[7]  += wc * qb.w;
                ft[8]  += wc * qc.x;  ft[9]  += wc * qc.y;
                ft[10] += wc * qc.z;  ft[11] += wc * qc.w;
            }
        }
    }

    // ---------------- stage x row: [feat(12), vemb(27), pad to 56 bf16] ----------------
    {
        uint32_t* xrow = s_x + tid * X_STRIDE;
        #pragma unroll
        for (int p = 0; p < 6; p++)
            xrow[p] = packbf2(ft[2 * p], ft[2 * p + 1]);
        #pragma unroll
        for (int p = 0; p < 14; p++) {
            __nv_bfloat162 b = s_v2[p];
            xrow[6 + p] = *(uint32_t*)&b;
        }
        #pragma unroll
        for (int p = 20; p < X_STRIDE; p++) xrow[p] = 0u;
    }
    __syncthreads();

    // ---------------- MLP via HMMA: per warp 32 samples = 2 m16 tiles ----------------
    const float B2x = __ldg(b2 + 0), B2y = __ldg(b2 + 1), B2z = __ldg(b2 + 2);
    float osum0 = 0.0f, osum1 = 0.0f, osum2 = 0.0f;
    const int wbase = warp * 32;

    #pragma unroll
    for (int mt = 0; mt < 2; mt++) {
        const int r0 = wbase + mt * 16 + gid;   // sample row for fragment rows 0-7
        const int r1 = r0 + 8;                  // rows 8-15

        // A0 fragments for layer0 (3 k-steps of 16 over K=48)
        uint32_t A0[3][4];
        #pragma unroll
        for (int ks = 0; ks < 3; ks++) {
            A0[ks][0] = s_x[r0 * X_STRIDE + 8 * ks + q];
            A0[ks][1] = s_x[r1 * X_STRIDE + 8 * ks + q];
            A0[ks][2] = s_x[r0 * X_STRIDE + 8 * ks + q + 4];
            A0[ks][3] = s_x[r1 * X_STRIDE + 8 * ks + q + 4];
        }

        // Layer0: 16 n8-tiles; C fragments convert in-register to layer1 A fragments.
        uint32_t A1[8][4];
        #pragma unroll
        for (int j = 0; j < 16; j++) {
            const int col = 8 * j + 2 * q;
            const int n   = 8 * j + gid;
            float2 bb = *(const float2*)&s_b0[col];
            float c0 = bb.x, c1 = bb.y, c2 = bb.x, c3 = bb.y;
            #pragma unroll
            for (int ks = 0; ks < 3; ks++) {
                uint32_t bb0 = s_w0p[n * W0P_STRIDE + 8 * ks + q];
                uint32_t bb1 = s_w0p[n * W0P_STRIDE + 8 * ks + q + 4];
                mma16816(c0, c1, c2, c3,
                         A0[ks][0], A0[ks][1], A0[ks][2], A0[ks][3], bb0, bb1);
            }
            uint32_t lo = packbf2(fmaxf(c0, 0.0f), fmaxf(c1, 0.0f));  // row r0
            uint32_t hi = packbf2(fmaxf(c2, 0.0f), fmaxf(c3, 0.0f));  // row r1
            const int ks1 = j >> 1;
            if ((j & 1) == 0) { A1[ks1][0] = lo; A1[ks1][1] = hi; }
            else              { A1[ks1][2] = lo; A1[ks1][3] = hi; }
        }

        // Layer1 (K=128, 8 k-steps) + fused layer2 epilogue
        float rs00 = 0.0f, rs01 = 0.0f, rs02 = 0.0f;  // row r0 partial rgb
        float rs10 = 0.0f, rs11 = 0.0f, rs12 = 0.0f;  // row r1
        #pragma unroll
        for (int j2 = 0; j2 < 16; j2++) {
            const int col = 8 * j2 + 2 * q;
            const int n   = 8 * j2 + gid;
            float2 bb = *(const float2*)&s_b1[col];
            float c0 = bb.x, c1 = bb.y, c2 = bb.x, c3 = bb.y;
            #pragma unroll
            for (int ks = 0; ks < 8; ks++) {
                uint32_t bb0 = s_w1p[n * W1P_STRIDE + 8 * ks + q];
                uint32_t bb1 = s_w1p[n * W1P_STRIDE + 8 * ks + q + 4];
                mma16816(c0, c1, c2, c3,
                         A1[ks][0], A1[ks][1], A1[ks][2], A1[ks][3], bb0, bb1);
            }
            float4 wA = s_w2p[col];
            float4 wB = s_w2p[col + 1];
            float a0 = fmaxf(c0, 0.0f), a1 = fmaxf(c1, 0.0f);
            float a2 = fmaxf(c2, 0.0f), a3 = fmaxf(c3, 0.0f);
            rs00 += a0 * wA.x + a1 * wB.x;
            rs01 += a0 * wA.y + a1 * wB.y;
            rs02 += a0 * wA.z + a1 * wB.z;
            rs10 += a2 * wA.x + a3 * wB.x;
            rs11 += a2 * wA.y + a3 * wB.y;
            rs12 += a2 * wA.z + a3 * wB.z;
        }

        // quad reduction (cols are spread over the 4 quad lanes)
        #pragma unroll
        for (int off = 1; off < 4; off <<= 1) {
            rs00 += __shfl_xor_sync(0xffffffffu, rs00, off);
            rs01 += __shfl_xor_sync(0xffffffffu, rs01, off);
            rs02 += __shfl_xor_sync(0xffffffffu, rs02, off);
            rs10 += __shfl_xor_sync(0xffffffffu, rs10, off);
            rs11 += __shfl_xor_sync(0xffffffffu, rs11, off);
            rs12 += __shfl_xor_sync(0xffffffffu, rs12, off);
        }

        if (q == 0) {
            float wg0 = s_wgt[r0], wg1 = s_wgt[r1];
            osum0 += wg0 * (1.0f / (1.0f + expf(-(rs00 + B2x))))
                   + wg1 * (1.0f / (1.0f + expf(-(rs10 + B2x))));
            osum1 += wg0 * (1.0f / (1.0f + expf(-(rs01 + B2y))))
                   + wg1 * (1.0f / (1.0f + expf(-(rs11 + B2y))));
            osum2 += wg0 * (1.0f / (1.0f + expf(-(rs02 + B2z))))
                   + wg1 * (1.0f / (1.0f + expf(-(rs12 + B2z))));
        }
    }

    // ---------------- reduce 3-vector over warp, then block ----------------
    #pragma unroll
    for (int s = 16; s > 0; s >>= 1) {
        osum0 += __shfl_down_sync(0xffffffffu, osum0, s);
        osum1 += __shfl_down_sync(0xffffffffu, osum1, s);
        osum2 += __shfl_down_sync(0xffffffffu, osum2, s);
    }
    if (lane == 0) {
        s_red[warp * 3 + 0] = osum0;
        s_red[warp * 3 + 1] = osum1;
        s_red[warp * 3 + 2] = osum2;
    }
    __syncthreads();
    if (tid == 0) {
        float a0 = 0.0f, a1 = 0.0f, a2 = 0.0f;
        #pragma unroll
        for (int w = 0; w < 8; w++) {
            a0 += s_red[w * 3 + 0];
            a1 += s_red[w * 3 + 1];
            a2 += s_red[w * 3 + 2];
        }
        out[ray * 3 + 0] = a0 + ainv_last;
        out[ray * 3 + 1] = a1 + ainv_last;
        out[ray * 3 + 2] = a2 + ainv_last;
    }
}

extern "C" void kernel_launch(void* const* d_in, const int* in_sizes, int n_in,
                              void* d_out, int out_size)
{
    const float* ray_pts  = (const float*)d_in[0];
    const float* viewdirs = (const float*)d_in[1];
    const float* dgrid    = (const float*)d_in[2];
    const float* k0       = (const float*)d_in[3];
    const float* w0       = (const float*)d_in[4];
    const float* b0       = (const float*)d_in[5];
    const float* w1       = (const float*)d_in[6];
    const float* b1       = (const float*)d_in[7];
    const float* w2       = (const float*)d_in[8];
    const float* b2       = (const float*)d_in[9];
    float* out = (float*)d_out;

    cudaFuncSetAttribute(dvgo_hmma_kernel,
                         cudaFuncAttributeMaxDynamicSharedMemorySize, SMEM_DYN);
    dvgo_hmma_kernel<<<RAYS, 256, SMEM_DYN>>>(
        ray_pts, viewdirs, dgrid, k0, w0, b0, w1, b1, w2, b2, out);
}

// round 10
// speedup vs baseline: 2.6628x; 1.0005x over previous
#include <cuda_runtime.h>
#include <cuda_bf16.h>
#include <cstdint>
#include <math.h>

#define RAYS    8192
#define SAMPLES 256
#define GRIDN   160
#define ACT_SHIFT (-13.815509557964274f)

// ---------------- SMEM layout (bytes) ----------------
// strides chosen so B-fragment LDS (n varies by lane>>2) hits distinct banks:
// word-stride % 32 == 4  ->  bank = 4*gid + q  (all 32 lanes distinct)
#define W1P_STRIDE 68    // words per n-row (64 data + pad)
#define W0P_STRIDE 28    // words per n-row (24 data + pad)
#define X_STRIDE   28    // words per sample row (20 data + pad)

#define OFF_W1P  0                        // 128*68*4 = 34816
#define OFF_W0P  34816                    // 128*28*4 = 14336
#define OFF_X    49152                    // 256*28*4 = 28672
#define OFF_B0   77824                    // 512
#define OFF_B1   78336                    // 512
#define OFF_W2P  78848                    // float4[128] = 2048
#define OFF_SCA  80896                    // 1024
#define OFF_SCB  81920                    // 1024
#define OFF_WGT  82944                    // 1024
#define OFF_VEMF 83968                    // 128
#define OFF_V2   84096                    // 64
#define OFF_RED  84160                    // 96
#define SMEM_DYN 84256

__device__ __forceinline__ void mma16816(float& c0, float& c1, float& c2, float& c3,
                                         uint32_t a0, uint32_t a1, uint32_t a2, uint32_t a3,
                                         uint32_t b0, uint32_t b1) {
    asm volatile("mma.sync.aligned.m16n8k16.row.col.f32.bf16.bf16.f32 "
                 "{%0,%1,%2,%3}, {%4,%5,%6,%7}, {%8,%9}, {%0,%1,%2,%3};"
                 : "+f"(c0), "+f"(c1), "+f"(c2), "+f"(c3)
                 : "r"(a0), "r"(a1), "r"(a2), "r"(a3), "r"(b0), "r"(b1));
}

__device__ __forceinline__ uint32_t packbf2(float lo, float hi) {
    __nv_bfloat162 b = __floats2bfloat162_rn(lo, hi);
    return *(uint32_t*)&b;
}

extern "C" __global__ void __launch_bounds__(256, 2)
dvgo_hmma_kernel(const float* __restrict__ ray_pts,
                 const float* __restrict__ viewdirs,
                 const float* __restrict__ dgrid,
                 const float* __restrict__ k0,
                 const float* __restrict__ w0,
                 const float* __restrict__ b0,
                 const float* __restrict__ w1,
                 const float* __restrict__ b1,
                 const float* __restrict__ w2,
                 const float* __restrict__ b2,
                 float* __restrict__ out)
{
    extern __shared__ char smem[];
    uint32_t* s_w1p = (uint32_t*)(smem + OFF_W1P);
    uint32_t* s_w0p = (uint32_t*)(smem + OFF_W0P);
    uint32_t* s_x   = (uint32_t*)(smem + OFF_X);
    float*    s_b0  = (float*)(smem + OFF_B0);
    float*    s_b1  = (float*)(smem + OFF_B1);
    float4*   s_w2p = (float4*)(smem + OFF_W2P);
    float*    sA    = (float*)(smem + OFF_SCA);
    float*    sB    = (float*)(smem + OFF_SCB);
    float*    s_wgt = (float*)(smem + OFF_WGT);
    float*    s_vf  = (float*)(smem + OFF_VEMF);
    __nv_bfloat162* s_v2 = (__nv_bfloat162*)(smem + OFF_V2);
    float*    s_red = (float*)(smem + OFF_RED);

    const int tid = threadIdx.x;
    const int ray = blockIdx.x;
    const int lane = tid & 31;
    const int warp = tid >> 5;
    const int gid = lane >> 2;     // group id (row within 8)
    const int q   = lane & 3;      // quad lane

    // ---------------- stage weights (k-paired bf16x2, transposed to n-major) ----------------
    // s_w1p[n*68 + kp] = (w1[2kp][n], w1[2kp+1][n])
    for (int i = tid; i < 128 * 64; i += 256) {
        int n = i & 127, kp = i >> 7;
        s_w1p[n * W1P_STRIDE + kp] = packbf2(w1[(2 * kp) * 128 + n],
                                             (w1[(2 * kp + 1) * 128 + n]));
    }
    // s_w0p[n*28 + kp] = (w0[2kp][n], w0[2kp+1][n]); k>=39 zero (in_dim=39, K padded to 48)
    for (int i = tid; i < 128 * 24; i += 256) {
        int n = i & 127, kp = i >> 7;
        int ka = 2 * kp, kb = 2 * kp + 1;
        float lo = (ka < 39) ? w0[ka * 128 + n] : 0.0f;
        float hi = (kb < 39) ? w0[kb * 128 + n] : 0.0f;
        s_w0p[n * W0P_STRIDE + kp] = packbf2(lo, hi);
    }
    if (tid < 128) {
        s_b0[tid] = b0[tid];
        s_b1[tid] = b1[tid];
        float4 w; w.x = w2[tid * 3]; w.y = w2[tid * 3 + 1]; w.z = w2[tid * 3 + 2]; w.w = 0.0f;
        s_w2p[tid] = w;
    }

    // ---------------- view embedding (per ray) ----------------
    if (tid < 28) {
        float vx = viewdirs[ray * 3 + 0];
        float vy = viewdirs[ray * 3 + 1];
        float vz = viewdirs[ray * 3 + 2];
        float inv = 1.0f / (sqrtf(vx * vx + vy * vy + vz * vz) + 1e-10f);
        float dd[3] = {vx * inv, vy * inv, vz * inv};
        float val;
        if (tid < 3)       val = dd[tid];
        else if (tid < 15) { int m = tid - 3;  val = sinf(dd[m >> 2] * (float)(1 << (m & 3))); }
        else if (tid < 27) { int m = tid - 15; val = cosf(dd[m >> 2] * (float)(1 << (m & 3))); }
        else               val = 0.0f;
        s_vf[tid] = val;
    }

    // ---------------- density trilinear + alpha (fp32, accuracy-critical) ----------------
    const int pidx = (ray * SAMPLES + tid) * 3;
    float px = ray_pts[pidx + 0];
    float py = ray_pts[pidx + 1];
    float pz = ray_pts[pidx + 2];

    float gx = fminf(fmaxf(px, 0.0f), 1.0f) * 159.0f;
    float gy = fminf(fmaxf(py, 0.0f), 1.0f) * 159.0f;
    float gz = fminf(fmaxf(pz, 0.0f), 1.0f) * 159.0f;
    int ix = (int)floorf(gx); ix = max(0, min(ix, 158));
    int iy = (int)floorf(gy); iy = max(0, min(iy, 158));
    int iz = (int)floorf(gz); iz = max(0, min(iz, 158));
    float fx = gx - (float)ix, fy = gy - (float)iy, fz = gz - (float)iz;

    const int base = (ix * GRIDN + iy) * GRIDN + iz;
    const float wx0 = 1.0f - fx, wx1 = fx;
    const float wy0 = 1.0f - fy, wy1 = fy;
    const float wz0 = 1.0f - fz, wz1 = fz;
    const int XS = GRIDN * GRIDN;

    float d000 = __ldg(dgrid + base);
    float d001 = __ldg(dgrid + base + 1);
    float d010 = __ldg(dgrid + base + GRIDN);
    float d011 = __ldg(dgrid + base + GRIDN + 1);
    float d100 = __ldg(dgrid + base + XS);
    float d101 = __ldg(dgrid + base + XS + 1);
    float d110 = __ldg(dgrid + base + XS + GRIDN);
    float d111 = __ldg(dgrid + base + XS + GRIDN + 1);

    float den = wx0 * (wy0 * (wz0 * d000 + wz1 * d001) +
                       wy1 * (wz0 * d010 + wz1 * d011)) +
                wx1 * (wy0 * (wz0 * d100 + wz1 * d101) +
                       wy1 * (wz0 * d110 + wz1 * d111));

    float e = expf(den + ACT_SHIFT);
    float alpha = 1.0f - 1.0f / sqrtf(1.0f + e);
    float t = 1.0f - alpha + 1e-10f;
    sA[tid] = t;
    __syncthreads();
    if (tid < 14) s_v2[tid] = __floats2bfloat162_rn(s_vf[2 * tid], s_vf[2 * tid + 1]);

    // ---------------- cumprod scan ----------------
    float v = t;
    float* cur = sA;
    float* nxt = sB;
    #pragma unroll
    for (int off = 1; off < SAMPLES; off <<= 1) {
        if (tid >= off) v *= cur[tid - off];
        nxt[tid] = v;
        __syncthreads();
        float* tmp = cur; cur = nxt; nxt = tmp;
    }
    float T_excl    = (tid == 0) ? 1.0f : cur[tid - 1];
    float ainv_last = cur[SAMPLES - 1];
    s_wgt[tid] = alpha * T_excl;

    // ---------------- feature trilinear (12 ch) ----------------
    const float4* k0v = (const float4*)k0;
    float ft[12];
    #pragma unroll
    for (int c = 0; c < 12; c++) ft[c] = 0.0f;
    #pragma unroll
    for (int cx = 0; cx < 2; cx++) {
        float wxa = cx ? wx1 : wx0;
        #pragma unroll
        for (int cy = 0; cy < 2; cy++) {
            float wxy = wxa * (cy ? wy1 : wy0);
            #pragma unroll
            for (int cz = 0; cz < 2; cz++) {
                float wc = wxy * (cz ? wz1 : wz0);
                int idx = base + cx * XS + cy * GRIDN + cz;
                int b3 = idx * 3;
                float4 qa = __ldg(k0v + b3);
                float4 qb = __ldg(k0v + b3 + 1);
                float4 qc = __ldg(k0v + b3 + 2);
                ft[0]  += wc * qa.x;  ft[1]  += wc * qa.y;
                ft[2]  += wc * qa.z;  ft[3]  += wc * qa.w;
                ft[4]  += wc * qb.x;  ft[5]  += wc * qb.y;
                ft[6]  += wc * qb.z;  ft[7]  += wc * qb.w;
                ft[8]  += wc * qc.x;  ft[9]  += wc * qc.y;
                ft[10] += wc * qc.z;  ft[11] += wc * qc.w;
            }
        }
    }

    // ---------------- stage x row: [feat(12), vemb(27), pad to 56 bf16] ----------------
    {
        uint32_t* xrow = s_x + tid * X_STRIDE;
        #pragma unroll
        for (int p = 0; p < 6; p++)
            xrow[p] = packbf2(ft[2 * p], ft[2 * p + 1]);
        #pragma unroll
        for (int p = 0; p < 14; p++) {
            __nv_bfloat162 b = s_v2[p];
            xrow[6 + p] = *(uint32_t*)&b;
        }
        #pragma unroll
        for (int p = 20; p < X_STRIDE; p++) xrow[p] = 0u;
    }
    __syncthreads();

    // ---------------- MLP via HMMA: per warp 32 samples = 2 m16 tiles ----------------
    const float B2x = __ldg(b2 + 0), B2y = __ldg(b2 + 1), B2z = __ldg(b2 + 2);
    float osum0 = 0.0f, osum1 = 0.0f, osum2 = 0.0f;
    const int wbase = warp * 32;

    #pragma unroll
    for (int mt = 0; mt < 2; mt++) {
        const int r0 = wbase + mt * 16 + gid;   // sample row for fragment rows 0-7
        const int r1 = r0 + 8;                  // rows 8-15

        // A0 fragments for layer0 (3 k-steps of 16 over K=48)
        uint32_t A0[3][4];
        #pragma unroll
        for (int ks = 0; ks < 3; ks++) {
            A0[ks][0] = s_x[r0 * X_STRIDE + 8 * ks + q];
            A0[ks][1] = s_x[r1 * X_STRIDE + 8 * ks + q];
            A0[ks][2] = s_x[r0 * X_STRIDE + 8 * ks + q + 4];
            A0[ks][3] = s_x[r1 * X_STRIDE + 8 * ks + q + 4];
        }

        // Layer0: 16 n8-tiles; C fragments convert in-register to layer1 A fragments.
        uint32_t A1[8][4];
        #pragma unroll
        for (int j = 0; j < 16; j++) {
            const int col = 8 * j + 2 * q;
            const int n   = 8 * j + gid;
            float2 bb = *(const float2*)&s_b0[col];
            float c0 = bb.x, c1 = bb.y, c2 = bb.x, c3 = bb.y;
            #pragma unroll
            for (int ks = 0; ks < 3; ks++) {
                uint32_t bb0 = s_w0p[n * W0P_STRIDE + 8 * ks + q];
                uint32_t bb1 = s_w0p[n * W0P_STRIDE + 8 * ks + q + 4];
                mma16816(c0, c1, c2, c3,
                         A0[ks][0], A0[ks][1], A0[ks][2], A0[ks][3], bb0, bb1);
            }
            uint32_t lo = packbf2(fmaxf(c0, 0.0f), fmaxf(c1, 0.0f));  // row r0
            uint32_t hi = packbf2(fmaxf(c2, 0.0f), fmaxf(c3, 0.0f));  // row r1
            const int ks1 = j >> 1;
            if ((j & 1) == 0) { A1[ks1][0] = lo; A1[ks1][1] = hi; }
            else              { A1[ks1][2] = lo; A1[ks1][3] = hi; }
        }

        // Layer1 (K=128, 8 k-steps) + fused layer2 epilogue
        float rs00 = 0.0f, rs01 = 0.0f, rs02 = 0.0f;  // row r0 partial rgb
        float rs10 = 0.0f, rs11 = 0.0f, rs12 = 0.0f;  // row r1
        #pragma unroll
        for (int j2 = 0; j2 < 16; j2++) {
            const int col = 8 * j2 + 2 * q;
            const int n   = 8 * j2 + gid;
            float2 bb = *(const float2*)&s_b1[col];
            float c0 = bb.x, c1 = bb.y, c2 = bb.x, c3 = bb.y;
            #pragma unroll
            for (int ks = 0; ks < 8; ks++) {
                uint32_t bb0 = s_w1p[n * W1P_STRIDE + 8 * ks + q];
                uint32_t bb1 = s_w1p[n * W1P_STRIDE + 8 * ks + q + 4];
                mma16816(c0, c1, c2, c3,
                         A1[ks][0], A1[ks][1], A1[ks][2], A1[ks][3], bb0, bb1);
            }
            float4 wA = s_w2p[col];
            float4 wB = s_w2p[col + 1];
            float a0 = fmaxf(c0, 0.0f), a1 = fmaxf(c1, 0.0f);
            float a2 = fmaxf(c2, 0.0f), a3 = fmaxf(c3, 0.0f);
            rs00 += a0 * wA.x + a1 * wB.x;
            rs01 += a0 * wA.y + a1 * wB.y;
            rs02 += a0 * wA.z + a1 * wB.z;
            rs10 += a2 * wA.x + a3 * wB.x;
            rs11 += a2 * wA.y + a3 * wB.y;
            rs12 += a2 * wA.z + a3 * wB.z;
        }

        // quad reduction (cols are spread over the 4 quad lanes)
        #pragma unroll
        for (int off = 1; off < 4; off <<= 1) {
            rs00 += __shfl_xor_sync(0xffffffffu, rs00, off);
            rs01 += __shfl_xor_sync(0xffffffffu, rs01, off);
            rs02 += __shfl_xor_sync(0xffffffffu, rs02, off);
            rs10 += __shfl_xor_sync(0xffffffffu, rs10, off);
            rs11 += __shfl_xor_sync(0xffffffffu, rs11, off);
            rs12 += __shfl_xor_sync(0xffffffffu, rs12, off);
        }

        if (q == 0) {
            float wg0 = s_wgt[r0], wg1 = s_wgt[r1];
            osum0 += wg0 * (1.0f / (1.0f + expf(-(rs00 + B2x))))
                   + wg1 * (1.0f / (1.0f + expf(-(rs10 + B2x))));
            osum1 += wg0 * (1.0f / (1.0f + expf(-(rs01 + B2y))))
                   + wg1 * (1.0f / (1.0f + expf(-(rs11 + B2y))));
            osum2 += wg0 * (1.0f / (1.0f + expf(-(rs02 + B2z))))
                   + wg1 * (1.0f / (1.0f + expf(-(rs12 + B2z))));
        }
    }

    // ---------------- reduce 3-vector over warp, then block ----------------
    #pragma unroll
    for (int s = 16; s > 0; s >>= 1) {
        osum0 += __shfl_down_sync(0xffffffffu, osum0, s);
        osum1 += __shfl_down_sync(0xffffffffu, osum1, s);
        osum2 += __shfl_down_sync(0xffffffffu, osum2, s);
    }
    if (lane == 0) {
        s_red[warp * 3 + 0] = osum0;
        s_red[warp * 3 + 1] = osum1;
        s_red[warp * 3 + 2] = osum2;
    }
    __syncthreads();
    if (tid == 0) {
        float a0 = 0.0f, a1 = 0.0f, a2 = 0.0f;
        #pragma unroll
        for (int w = 0; w < 8; w++) {
            a0 += s_red[w * 3 + 0];
            a1 += s_red[w * 3 + 1];
            a2 += s_red[w * 3 + 2];
        }
        out[ray * 3 + 0] = a0 + ainv_last;
        out[ray * 3 + 1] = a1 + ainv_last;
        out[ray * 3 + 2] = a2 + ainv_last;
    }
}

extern "C" void kernel_launch(void* const* d_in, const int* in_sizes, int n_in,
                              void* d_out, int out_size)
{
    const float* ray_pts  = (const float*)d_in[0];
    const float* viewdirs = (const float*)d_in[1];
    const float* dgrid    = (const float*)d_in[2];
    const float* k0       = (const float*)d_in[3];
    const float* w0       = (const float*)d_in[4];
    const float* b0       = (const float*)d_in[5];
    const float* w1       = (const float*)d_in[6];
    const float* b1       = (const float*)d_in[7];
    const float* w2       = (const float*)d_in[8];
    const float* b2       = (const float*)d_in[9];
    float* out = (float*)d_out;

    cudaFuncSetAttribute(dvgo_hmma_kernel,
                         cudaFuncAttributeMaxDynamicSharedMemorySize, SMEM_DYN);
    dvgo_hmma_kernel<<<RAYS, 256, SMEM_DYN>>>(
        ray_pts, viewdirs, dgrid, k0, w0, b0, w1, b1, w2, b2, out);
}

// round 11
// speedup vs baseline: 2.6637x; 1.0003x over previous
#include <cuda_runtime.h>
#include <cuda_bf16.h>
#include <cstdint>
#include <math.h>

#define RAYS    8192
#define SAMPLES 256
#define GRIDN   160
#define ACT_SHIFT (-13.815509557964274f)

// ---------------- SMEM layout (bytes) ----------------
// strides chosen so B-fragment LDS (n varies by lane>>2) hits distinct banks:
// word-stride % 32 == 4  ->  bank = 4*gid + q  (all 32 lanes distinct)
#define W1P_STRIDE 68    // words per n-row (64 data + pad)
#define W0P_STRIDE 28    // words per n-row (24 data + pad)
#define X_STRIDE   28    // words per sample row (20 data + pad)

#define OFF_W1P  0                        // 128*68*4 = 34816
#define OFF_W0P  34816                    // 128*28*4 = 14336
#define OFF_X    49152                    // 256*28*4 = 28672
#define OFF_B0   77824                    // 512
#define OFF_B1   78336                    // 512
#define OFF_W2P  78848                    // float4[128] = 2048
#define OFF_SCA  80896                    // 1024
#define OFF_SCB  81920                    // 1024
#define OFF_WGT  82944                    // 1024
#define OFF_VEMF 83968                    // 128
#define OFF_V2   84096                    // 64
#define OFF_RED  84160                    // 96
#define SMEM_DYN 84256

__device__ __forceinline__ void mma16816(float& c0, float& c1, float& c2, float& c3,
                                         uint32_t a0, uint32_t a1, uint32_t a2, uint32_t a3,
                                         uint32_t b0, uint32_t b1) {
    asm volatile("mma.sync.aligned.m16n8k16.row.col.f32.bf16.bf16.f32 "
                 "{%0,%1,%2,%3}, {%4,%5,%6,%7}, {%8,%9}, {%0,%1,%2,%3};"
                 : "+f"(c0), "+f"(c1), "+f"(c2), "+f"(c3)
                 : "r"(a0), "r"(a1), "r"(a2), "r"(a3), "r"(b0), "r"(b1));
}

__device__ __forceinline__ uint32_t packbf2(float lo, float hi) {
    __nv_bfloat162 b = __floats2bfloat162_rn(lo, hi);
    return *(uint32_t*)&b;
}

extern "C" __global__ void __launch_bounds__(256, 2)
dvgo_hmma_kernel(const float* __restrict__ ray_pts,
                 const float* __restrict__ viewdirs,
                 const float* __restrict__ dgrid,
                 const float* __restrict__ k0,
                 const float* __restrict__ w0,
                 const float* __restrict__ b0,
                 const float* __restrict__ w1,
                 const float* __restrict__ b1,
                 const float* __restrict__ w2,
                 const float* __restrict__ b2,
                 float* __restrict__ out)
{
    extern __shared__ char smem[];
    uint32_t* s_w1p = (uint32_t*)(smem + OFF_W1P);
    uint32_t* s_w0p = (uint32_t*)(smem + OFF_W0P);
    uint32_t* s_x   = (uint32_t*)(smem + OFF_X);
    float*    s_b0  = (float*)(smem + OFF_B0);
    float*    s_b1  = (float*)(smem + OFF_B1);
    float4*   s_w2p = (float4*)(smem + OFF_W2P);
    float*    sA    = (float*)(smem + OFF_SCA);
    float*    sB    = (float*)(smem + OFF_SCB);
    float*    s_wgt = (float*)(smem + OFF_WGT);
    float*    s_vf  = (float*)(smem + OFF_VEMF);
    __nv_bfloat162* s_v2 = (__nv_bfloat162*)(smem + OFF_V2);
    float*    s_red = (float*)(smem + OFF_RED);

    const int tid = threadIdx.x;
    const int ray = blockIdx.x;
    const int lane = tid & 31;
    const int warp = tid >> 5;
    const int gid = lane >> 2;     // group id (row within 8)
    const int q   = lane & 3;      // quad lane

    // ---------------- stage weights (k-paired bf16x2, transposed to n-major) ----------------
    // s_w1p[n*68 + kp] = (w1[2kp][n], w1[2kp+1][n])
    for (int i = tid; i < 128 * 64; i += 256) {
        int n = i & 127, kp = i >> 7;
        s_w1p[n * W1P_STRIDE + kp] = packbf2(w1[(2 * kp) * 128 + n],
                                             (w1[(2 * kp + 1) * 128 + n]));
    }
    // s_w0p[n*28 + kp] = (w0[2kp][n], w0[2kp+1][n]); k>=39 zero (in_dim=39, K padded to 48)
    for (int i = tid; i < 128 * 24; i += 256) {
        int n = i & 127, kp = i >> 7;
        int ka = 2 * kp, kb = 2 * kp + 1;
        float lo = (ka < 39) ? w0[ka * 128 + n] : 0.0f;
        float hi = (kb < 39) ? w0[kb * 128 + n] : 0.0f;
        s_w0p[n * W0P_STRIDE + kp] = packbf2(lo, hi);
    }
    if (tid < 128) {
        s_b0[tid] = b0[tid];
        s_b1[tid] = b1[tid];
        float4 w; w.x = w2[tid * 3]; w.y = w2[tid * 3 + 1]; w.z = w2[tid * 3 + 2]; w.w = 0.0f;
        s_w2p[tid] = w;
    }

    // ---------------- view embedding (per ray) ----------------
    if (tid < 28) {
        float vx = viewdirs[ray * 3 + 0];
        float vy = viewdirs[ray * 3 + 1];
        float vz = viewdirs[ray * 3 + 2];
        float inv = 1.0f / (sqrtf(vx * vx + vy * vy + vz * vz) + 1e-10f);
        float dd[3] = {vx * inv, vy * inv, vz * inv};
        float val;
        if (tid < 3)       val = dd[tid];
        else if (tid < 15) { int m = tid - 3;  val = sinf(dd[m >> 2] * (float)(1 << (m & 3))); }
        else if (tid < 27) { int m = tid - 15; val = cosf(dd[m >> 2] * (float)(1 << (m & 3))); }
        else               val = 0.0f;
        s_vf[tid] = val;
    }

    // ---------------- density trilinear + alpha (fp32, accuracy-critical) ----------------
    const int pidx = (ray * SAMPLES + tid) * 3;
    float px = ray_pts[pidx + 0];
    float py = ray_pts[pidx + 1];
    float pz = ray_pts[pidx + 2];

    float gx = fminf(fmaxf(px, 0.0f), 1.0f) * 159.0f;
    float gy = fminf(fmaxf(py, 0.0f), 1.0f) * 159.0f;
    float gz = fminf(fmaxf(pz, 0.0f), 1.0f) * 159.0f;
    int ix = (int)floorf(gx); ix = max(0, min(ix, 158));
    int iy = (int)floorf(gy); iy = max(0, min(iy, 158));
    int iz = (int)floorf(gz); iz = max(0, min(iz, 158));
    float fx = gx - (float)ix, fy = gy - (float)iy, fz = gz - (float)iz;

    const int base = (ix * GRIDN + iy) * GRIDN + iz;
    const float wx0 = 1.0f - fx, wx1 = fx;
    const float wy0 = 1.0f - fy, wy1 = fy;
    const float wz0 = 1.0f - fz, wz1 = fz;
    const int XS = GRIDN * GRIDN;

    float d000 = __ldg(dgrid + base);
    float d001 = __ldg(dgrid + base + 1);
    float d010 = __ldg(dgrid + base + GRIDN);
    float d011 = __ldg(dgrid + base + GRIDN + 1);
    float d100 = __ldg(dgrid + base + XS);
    float d101 = __ldg(dgrid + base + XS + 1);
    float d110 = __ldg(dgrid + base + XS + GRIDN);
    float d111 = __ldg(dgrid + base + XS + GRIDN + 1);

    float den = wx0 * (wy0 * (wz0 * d000 + wz1 * d001) +
                       wy1 * (wz0 * d010 + wz1 * d011)) +
                wx1 * (wy0 * (wz0 * d100 + wz1 * d101) +
                       wy1 * (wz0 * d110 + wz1 * d111));

    float e = expf(den + ACT_SHIFT);
    float alpha = 1.0f - 1.0f / sqrtf(1.0f + e);
    float t = 1.0f - alpha + 1e-10f;
    sA[tid] = t;
    __syncthreads();
    if (tid < 14) s_v2[tid] = __floats2bfloat162_rn(s_vf[2 * tid], s_vf[2 * tid + 1]);

    // ---------------- cumprod scan ----------------
    float v = t;
    float* cur = sA;
    float* nxt = sB;
    #pragma unroll
    for (int off = 1; off < SAMPLES; off <<= 1) {
        if (tid >= off) v *= cur[tid - off];
        nxt[tid] = v;
        __syncthreads();
        float* tmp = cur; cur = nxt; nxt = tmp;
    }
    float T_excl    = (tid == 0) ? 1.0f : cur[tid - 1];
    float ainv_last = cur[SAMPLES - 1];
    s_wgt[tid] = alpha * T_excl;

    // ---------------- feature trilinear (12 ch) ----------------
    const float4* k0v = (const float4*)k0;
    float ft[12];
    #pragma unroll
    for (int c = 0; c < 12; c++) ft[c] = 0.0f;
    #pragma unroll
    for (int cx = 0; cx < 2; cx++) {
        float wxa = cx ? wx1 : wx0;
        #pragma unroll
        for (int cy = 0; cy < 2; cy++) {
            float wxy = wxa * (cy ? wy1 : wy0);
            #pragma unroll
            for (int cz = 0; cz < 2; cz++) {
                float wc = wxy * (cz ? wz1 : wz0);
                int idx = base + cx * XS + cy * GRIDN + cz;
                int b3 = idx * 3;
                float4 qa = __ldg(k0v + b3);
                float4 qb = __ldg(k0v + b3 + 1);
                float4 qc = __ldg(k0v + b3 + 2);
                ft[0]  += wc * qa.x;  ft[1]  += wc * qa.y;
                ft[2]  += wc * qa.z;  ft[3]  += wc * qa.w;
                ft[4]  += wc * qb.x;  ft[5]  += wc * qb.y;
                ft[6]  += wc * qb.z;  ft[7]  += wc * qb.w;
                ft[8]  += wc * qc.x;  ft[9]  += wc * qc.y;
                ft[10] += wc * qc.z;  ft[11] += wc * qc.w;
            }
        }
    }

    // ---------------- stage x row: [feat(12), vemb(27), pad to 56 bf16] ----------------
    {
        uint32_t* xrow = s_x + tid * X_STRIDE;
        #pragma unroll
        for (int p = 0; p < 6; p++)
            xrow[p] = packbf2(ft[2 * p], ft[2 * p + 1]);
        #pragma unroll
        for (int p = 0; p < 14; p++) {
            __nv_bfloat162 b = s_v2[p];
            xrow[6 + p] = *(uint32_t*)&b;
        }
        #pragma unroll
        for (int p = 20; p < X_STRIDE; p++) xrow[p] = 0u;
    }
    __syncthreads();

    // ---------------- MLP via HMMA: per warp 32 samples = 2 m16 tiles ----------------
    const float B2x = __ldg(b2 + 0), B2y = __ldg(b2 + 1), B2z = __ldg(b2 + 2);
    float osum0 = 0.0f, osum1 = 0.0f, osum2 = 0.0f;
    const int wbase = warp * 32;

    #pragma unroll
    for (int mt = 0; mt < 2; mt++) {
        const int r0 = wbase + mt * 16 + gid;   // sample row for fragment rows 0-7
        const int r1 = r0 + 8;                  // rows 8-15

        // A0 fragments for layer0 (3 k-steps of 16 over K=48)
        uint32_t A0[3][4];
        #pragma unroll
        for (int ks = 0; ks < 3; ks++) {
            A0[ks][0] = s_x[r0 * X_STRIDE + 8 * ks + q];
            A0[ks][1] = s_x[r1 * X_STRIDE + 8 * ks + q];
            A0[ks][2] = s_x[r0 * X_STRIDE + 8 * ks + q + 4];
            A0[ks][3] = s_x[r1 * X_STRIDE + 8 * ks + q + 4];
        }

        // Layer0: 16 n8-tiles; C fragments convert in-register to layer1 A fragments.
        uint32_t A1[8][4];
        #pragma unroll
        for (int j = 0; j < 16; j++) {
            const int col = 8 * j + 2 * q;
            const int n   = 8 * j + gid;
            float2 bb = *(const float2*)&s_b0[col];
            float c0 = bb.x, c1 = bb.y, c2 = bb.x, c3 = bb.y;
            #pragma unroll
            for (int ks = 0; ks < 3; ks++) {
                uint32_t bb0 = s_w0p[n * W0P_STRIDE + 8 * ks + q];
                uint32_t bb1 = s_w0p[n * W0P_STRIDE + 8 * ks + q + 4];
                mma16816(c0, c1, c2, c3,
                         A0[ks][0], A0[ks][1], A0[ks][2], A0[ks][3], bb0, bb1);
            }
            uint32_t lo = packbf2(fmaxf(c0, 0.0f), fmaxf(c1, 0.0f));  // row r0
            uint32_t hi = packbf2(fmaxf(c2, 0.0f), fmaxf(c3, 0.0f));  // row r1
            const int ks1 = j >> 1;
            if ((j & 1) == 0) { A1[ks1][0] = lo; A1[ks1][1] = hi; }
            else              { A1[ks1][2] = lo; A1[ks1][3] = hi; }
        }

        // Layer1 (K=128, 8 k-steps) + fused layer2 epilogue
        float rs00 = 0.0f, rs01 = 0.0f, rs02 = 0.0f;  // row r0 partial rgb
        float rs10 = 0.0f, rs11 = 0.0f, rs12 = 0.0f;  // row r1
        #pragma unroll
        for (int j2 = 0; j2 < 16; j2++) {
            const int col = 8 * j2 + 2 * q;
            const int n   = 8 * j2 + gid;
            float2 bb = *(const float2*)&s_b1[col];
            float c0 = bb.x, c1 = bb.y, c2 = bb.x, c3 = bb.y;
            #pragma unroll
            for (int ks = 0; ks < 8; ks++) {
                uint32_t bb0 = s_w1p[n * W1P_STRIDE + 8 * ks + q];
                uint32_t bb1 = s_w1p[n * W1P_STRIDE + 8 * ks + q + 4];
                mma16816(c0, c1, c2, c3,
                         A1[ks][0], A1[ks][1], A1[ks][2], A1[ks][3], bb0, bb1);
            }
            float4 wA = s_w2p[col];
            float4 wB = s_w2p[col + 1];
            float a0 = fmaxf(c0, 0.0f), a1 = fmaxf(c1, 0.0f);
            float a2 = fmaxf(c2, 0.0f), a3 = fmaxf(c3, 0.0f);
            rs00 += a0 * wA.x + a1 * wB.x;
            rs01 += a0 * wA.y + a1 * wB.y;
            rs02 += a0 * wA.z + a1 * wB.z;
            rs10 += a2 * wA.x + a3 * wB.x;
            rs11 += a2 * wA.y + a3 * wB.y;
            rs12 += a2 * wA.z + a3 * wB.z;
        }

        // quad reduction (cols are spread over the 4 quad lanes)
        #pragma unroll
        for (int off = 1; off < 4; off <<= 1) {
            rs00 += __shfl_xor_sync(0xffffffffu, rs00, off);
            rs01 += __shfl_xor_sync(0xffffffffu, rs01, off);
            rs02 += __shfl_xor_sync(0xffffffffu, rs02, off);
            rs10 += __shfl_xor_sync(0xffffffffu, rs10, off);
            rs11 += __shfl_xor_sync(0xffffffffu, rs11, off);
            rs12 += __shfl_xor_sync(0xffffffffu, rs12, off);
        }

        if (q == 0) {
            float wg0 = s_wgt[r0], wg1 = s_wgt[r1];
            osum0 += wg0 * (1.0f / (1.0f + expf(-(rs00 + B2x))))
                   + wg1 * (1.0f / (1.0f + expf(-(rs10 + B2x))));
            osum1 += wg0 * (1.0f / (1.0f + expf(-(rs01 + B2y))))
                   + wg1 * (1.0f / (1.0f + expf(-(rs11 + B2y))));
            osum2 += wg0 * (1.0f / (1.0f + expf(-(rs02 + B2z))))
                   + wg1 * (1.0f / (1.0f + expf(-(rs12 + B2z))));
        }
    }

    // ---------------- reduce 3-vector over warp, then block ----------------
    #pragma unroll
    for (int s = 16; s > 0; s >>= 1) {
        osum0 += __shfl_down_sync(0xffffffffu, osum0, s);
        osum1 += __shfl_down_sync(0xffffffffu, osum1, s);
        osum2 += __shfl_down_sync(0xffffffffu, osum2, s);
    }
    if (lane == 0) {
        s_red[warp * 3 + 0] = osum0;
        s_red[warp * 3 + 1] = osum1;
        s_red[warp * 3 + 2] = osum2;
    }
    __syncthreads();
    if (tid == 0) {
        float a0 = 0.0f, a1 = 0.0f, a2 = 0.0f;
        #pragma unroll
        for (int w = 0; w < 8; w++) {
            a0 += s_red[w * 3 + 0];
            a1 += s_red[w * 3 + 1];
            a2 += s_red[w * 3 + 2];
        }
        out[ray * 3 + 0] = a0 + ainv_last;
        out[ray * 3 + 1] = a1 + ainv_last;
        out[ray * 3 + 2] = a2 + ainv_last;
    }
}

extern "C" void kernel_launch(void* const* d_in, const int* in_sizes, int n_in,
                              void* d_out, int out_size)
{
    const float* ray_pts  = (const float*)d_in[0];
    const float* viewdirs = (const float*)d_in[1];
    const float* dgrid    = (const float*)d_in[2];
    const float* k0       = (const float*)d_in[3];
    const float* w0       = (const float*)d_in[4];
    const float* b0       = (const float*)d_in[5];
    const float* w1       = (const float*)d_in[6];
    const float* b1       = (const float*)d_in[7];
    const float* w2       = (const float*)d_in[8];
    const float* b2       = (const float*)d_in[9];
    float* out = (float*)d_out;

    cudaFuncSetAttribute(dvgo_hmma_kernel,
                         cudaFuncAttributeMaxDynamicSharedMemorySize, SMEM_DYN);
    dvgo_hmma_kernel<<<RAYS, 256, SMEM_DYN>>>(
        ray_pts, viewdirs, dgrid, k0, w0, b0, w1, b1, w2, b2, out);
}